// round 10
// baseline (speedup 1.0000x reference)
#include <cuda_runtime.h>

// 2-layer LSTM (H=50), T=65536 serial steps, one persistent CTA, 448 threads.
// Dual-role warps, both busy in both windows (2 barriers/step):
//   mains (warps 0-6, R8 quad layout): on-path work only
//     A: y = bo + sum(parr); err; g1K = aarr[row] + w7K*err; act/shfl/cell1 -> sh1
//     B: r = Wih2@h1; g2K = qarr[row] + r; act/shfl/cell2 -> sh2, parr
//   helpers (warps 7-13, one gate row per lane): off-path dots
//     window1 (|| A): qarr[row] = bb2K + Whh2@h2(s-1)     (reads sh2)
//     window2 (|| B): aarr[row] = bb1K + Wih1@x(s+1) + Whh1@h1(s)
// Race audit: qarr written in [BAR_B(s-1),BAR_A(s)], read in [BAR_A(s),BAR_B(s)];
// aarr written in [BAR_A(s),BAR_B(s)], read in [BAR_B(s),BAR_A(s+1)]; sh2 read by
// helpers before BAR_A, written by mains after BAR_A. All disjoint.

#define HDIM     50
#define INP      8
#define CHUNK    1024
#define NTHREADS 448

typedef unsigned long long u64;

__device__ __forceinline__ u64 pk2(float lo, float hi) {
    u64 r; asm("mov.b64 %0, {%1,%2};" : "=l"(r) : "f"(lo), "f"(hi)); return r;
}
__device__ __forceinline__ float2 upk2(u64 v) {
    float2 f; asm("mov.b64 {%0,%1}, %2;" : "=f"(f.x), "=f"(f.y) : "l"(v)); return f;
}
__device__ __forceinline__ u64 ffma2(u64 a, u64 b, u64 c) {
    u64 d; asm("fma.rn.f32x2 %0, %1, %2, %3;" : "=l"(d) : "l"(a), "l"(b), "l"(c)); return d;
}
__device__ __forceinline__ u64 add2(u64 a, u64 b) {
    u64 d; asm("add.rn.f32x2 %0, %1, %2;" : "=l"(d) : "l"(a), "l"(b)); return d;
}
__device__ __forceinline__ float tanha(float x) {
    float r; asm("tanh.approx.f32 %0, %1;" : "=f"(r) : "f"(x)); return r;
}

__global__ __launch_bounds__(NTHREADS, 1)
void lstm_r10_kernel(const float* __restrict__ input_seq,
                     const float* __restrict__ W_ih1, const float* __restrict__ W_hh1,
                     const float* __restrict__ b_ih1, const float* __restrict__ b_hh1,
                     const float* __restrict__ W_ih2, const float* __restrict__ W_hh2,
                     const float* __restrict__ b_ih2, const float* __restrict__ b_hh2,
                     const float* __restrict__ W_out, const float* __restrict__ b_out,
                     float* __restrict__ out, int T)
{
    __shared__ __align__(16) float sh1[56];     // h1(s), [50..55]=0
    __shared__ __align__(16) float sh2[56];     // h2(s), [50..55]=0
    __shared__ __align__(16) float parr[56];    // wout[u]*h2[u], [50..55]=0
    __shared__ __align__(16) float qarr[200];   // K*(bb2 + Whh2@h2(s-1))
    __shared__ __align__(16) float aarr[200];   // K*(bb1 + Wih1@x + Whh1@h1)
    __shared__ __align__(16) float xbuf[(CHUNK + 1) * INP];

    const int t = threadIdx.x;
    const int w = t >> 5;
    const int l = t & 31;
    const bool mainW = (w < 7);

    // ---- main-warp lane decode (R8 quad layout)
    const int k = l >> 3;                 // gate kind
    const int j0 = l & 7;
    const int uraw = w * 8 + j0;
    const bool uvalid = mainW && (uraw < HDIM);
    const int u = (uraw < HDIM) ? uraw : (HDIM - 1);
    const int mrow = k * HDIM + u;

    // ---- helper-warp lane decode (one gate row per lane)
    const int qi = (w - 7) * 32 + l;
    const bool qact = (!mainW) && (qi < 200);
    const int qrow = (qi < 200) ? qi : 199;

    const int row = mainW ? mrow : qrow;
    const float actK = (row >= 100 && row < 150) ? 1.0f : 0.5f;
    const float actA = (row >= 100 && row < 150) ? 0.0f : 0.5f;
    const float bo = b_out[0];

    // ---- weights (disjoint live ranges between roles)
    u64 wi2[26];                 // mains: Wih2 row, K-folded
    u64 wh1[26], wh2[26], wx[3]; // helpers: K-folded
    float w7K = 0.0f, wout_u = 0.0f;
    float w6x = 0.0f, bb1K = 0.0f, bb2K = 0.0f;
    if (mainW) {
        const float* r3 = W_ih2 + row * HDIM;
        #pragma unroll
        for (int j = 0; j < 25; ++j) wi2[j] = pk2(actK * r3[2*j], actK * r3[2*j+1]);
        wi2[25] = 0ULL;
        w7K = actK * W_ih1[row * INP + 7];
        wout_u = W_out[u];
    } else {
        const float* r2 = W_hh1 + row * HDIM;
        const float* r4 = W_hh2 + row * HDIM;
        #pragma unroll
        for (int j = 0; j < 25; ++j) {
            wh1[j] = pk2(actK * r2[2*j], actK * r2[2*j+1]);
            wh2[j] = pk2(actK * r4[2*j], actK * r4[2*j+1]);
        }
        wh1[25] = 0ULL; wh2[25] = 0ULL;
        const float* r1 = W_ih1 + row * INP;
        wx[0] = pk2(actK * r1[0], actK * r1[1]);
        wx[1] = pk2(actK * r1[2], actK * r1[3]);
        wx[2] = pk2(actK * r1[4], actK * r1[5]);
        w6x = actK * r1[6];
        bb1K = actK * (b_ih1[row] + b_hh1[row]);
        bb2K = actK * (b_ih2[row] + b_hh2[row]);
    }

    // ---- init shared
    if (t < 56) { sh1[t] = 0.0f; sh2[t] = 0.0f; parr[t] = 0.0f; }

    // stage chunk 0
    {
        const float4* src = (const float4*)input_seq;
        float4* dst = (float4*)xbuf;
        int n4 = (CHUNK + 1) * 2;
        int rem4 = T * 2;
        if (rem4 < n4) n4 = rem4;
        for (int i = t; i < n4; i += NTHREADS) dst[i] = src[i];
    }
    __syncthreads();

    // prefill aarr(0) = bb1K + K*Wih1@x(0)[0..6]  (h1(-1)=0; sh1 zeroed)
    if (!mainW) {
        float4 xa = *(const float4*)(xbuf);
        float4 xb = *(const float4*)(xbuf + 4);
        u64 a0 = ffma2(wx[0], pk2(xa.x, xa.y), pk2(bb1K, 0.0f));
        u64 a1 = ffma2(wx[1], pk2(xa.z, xa.w), pk2(w6x * xb.z, 0.0f));
        a0 = ffma2(wx[2], pk2(xb.x, xb.y), a0);
        float2 f = upk2(add2(a0, a1));
        if (qact) aarr[qi] = f.x + f.y;
    }
    __syncthreads();

    float c1 = 0.0f, c2 = 0.0f, err = 0.0f, x7_use = 0.0f;

    #pragma unroll 1
    for (int s = 0; s < T; ++s) {
        const int lo = s & (CHUNK - 1);
        if (lo == 0 && s != 0) {
            // all prior xbuf readers done at BAR_B(s-1)
            const float4* src = (const float4*)(input_seq + (size_t)s * INP);
            float4* dst = (float4*)xbuf;
            int n4 = (CHUNK + 1) * 2;
            int rem4 = (T - s) * 2;
            if (rem4 < n4) n4 = rem4;
            for (int i = t; i < n4; i += NTHREADS) dst[i] = src[i];
            __syncthreads();
        }

        if (mainW) {
            // ---- phase A: y from parr, err, gates1 finish, cell1
            u64 p0 = pk2(0.0f, 0.0f), p1 = p0, p2 = p0, p3 = p0;
            const float4* pv = (const float4*)parr;
            #pragma unroll
            for (int j = 0; j < 6; ++j) {
                float4 ha = pv[2*j], hb = pv[2*j+1];
                p0 = add2(p0, pk2(ha.x, ha.y));
                p1 = add2(p1, pk2(ha.z, ha.w));
                p2 = add2(p2, pk2(hb.x, hb.y));
                p3 = add2(p3, pk2(hb.z, hb.w));
            }
            float4 hc = pv[12];
            p0 = add2(p0, pk2(hc.x, hc.y));
            p1 = add2(p1, pk2(hc.z, hc.w));
            float a1p = aarr[row];                         // K-scaled partial
            float2 pf = upk2(add2(add2(p0, p1), add2(p2, p3)));
            float y = bo + (pf.x + pf.y);                  // y(s-1)
            err = (s != 0) ? fmaf(0.1f, x7_use - y, 0.9f * err) : 0.0f;
            if (t == 0 && s != 0) out[s - 1] = y;
            float g1K = fmaf(w7K, err, a1p);
            float v0 = fmaf(tanha(g1K), actK, actA);
            float I = __shfl_sync(0xffffffffu, v0, j0);
            float F = __shfl_sync(0xffffffffu, v0, j0 + 8);
            float G = __shfl_sync(0xffffffffu, v0, j0 + 16);
            float O = __shfl_sync(0xffffffffu, v0, j0 + 24);
            c1 = fmaf(F, c1, I * G);
            float h1v = O * tanha(c1);
            if (k == 0 && uvalid) sh1[u] = h1v;
        } else {
            // ---- window1: qarr(s) = bb2K + K*Whh2 @ h2(s-1)
            u64 q0 = pk2(bb2K, 0.0f), q1 = pk2(0.0f, 0.0f);
            const float4* hv = (const float4*)sh2;
            #pragma unroll
            for (int j = 0; j < 13; ++j) {
                float4 h = hv[j];
                q0 = ffma2(wh2[2*j],     pk2(h.x, h.y), q0);
                q1 = ffma2(wh2[2*j + 1], pk2(h.z, h.w), q1);
            }
            float2 f = upk2(add2(q0, q1));
            if (qact) qarr[qi] = f.x + f.y;
        }
        __syncthreads();   // BAR_A: h1(s), qarr(s) ready

        if (mainW) {
            // ---- phase B: gates2 finish, cell2, publish h2 + parr
            float qv = qarr[row];
            u64 r0 = pk2(0.0f, 0.0f), r1 = r0, r2 = r0, r3 = r0;
            const float4* hv = (const float4*)sh1;
            #pragma unroll
            for (int j = 0; j < 6; ++j) {
                float4 ha = hv[2*j], hb = hv[2*j+1];
                r0 = ffma2(wi2[4*j],     pk2(ha.x, ha.y), r0);
                r1 = ffma2(wi2[4*j + 1], pk2(ha.z, ha.w), r1);
                r2 = ffma2(wi2[4*j + 2], pk2(hb.x, hb.y), r2);
                r3 = ffma2(wi2[4*j + 3], pk2(hb.z, hb.w), r3);
            }
            float4 hc = hv[12];
            r0 = ffma2(wi2[24], pk2(hc.x, hc.y), r0);
            r1 = ffma2(wi2[25], pk2(hc.z, hc.w), r1);
            float2 rf = upk2(add2(add2(r0, r1), add2(r2, r3)));
            float g2K = qv + (rf.x + rf.y);
            float v0 = fmaf(tanha(g2K), actK, actA);
            float I = __shfl_sync(0xffffffffu, v0, j0);
            float F = __shfl_sync(0xffffffffu, v0, j0 + 8);
            float G = __shfl_sync(0xffffffffu, v0, j0 + 16);
            float O = __shfl_sync(0xffffffffu, v0, j0 + 24);
            c2 = fmaf(F, c2, I * G);
            float h2v = O * tanha(c2);
            if (k == 0 && uvalid) {
                sh2[u] = h2v;
                parr[u] = wout_u * h2v;
            }
            x7_use = xbuf[lo * INP + 7];   // x(s)[7], for err at A(s+1)
        } else {
            // ---- window2: aarr(s+1) = bb1K + K*Wih1@x(s+1) + K*Whh1@h1(s)
            const float* xn = &xbuf[(lo + 1) * INP];
            float4 xa = *(const float4*)(xn);
            float4 xb = *(const float4*)(xn + 4);
            u64 a0 = ffma2(wx[0], pk2(xa.x, xa.y), pk2(bb1K, 0.0f));
            u64 a1 = ffma2(wx[1], pk2(xa.z, xa.w), pk2(w6x * xb.z, 0.0f));
            a0 = ffma2(wx[2], pk2(xb.x, xb.y), a0);
            const float4* hv = (const float4*)sh1;
            #pragma unroll
            for (int j = 0; j < 13; ++j) {
                float4 h = hv[j];
                a0 = ffma2(wh1[2*j],     pk2(h.x, h.y), a0);
                a1 = ffma2(wh1[2*j + 1], pk2(h.z, h.w), a1);
            }
            float2 f = upk2(add2(a0, a1));
            if (qact) aarr[qi] = f.x + f.y;
        }
        __syncthreads();   // BAR_B: h2(s), parr(s), aarr(s+1) ready
    }

    // epilogue: y(T-1) = bo + sum(parr)
    if (t == 0) {
        float y = bo;
        for (int j = 0; j < HDIM; ++j) y += parr[j];
        out[T - 1] = y;
    }
}

extern "C" void kernel_launch(void* const* d_in, const int* in_sizes, int n_in,
                              void* d_out, int out_size) {
    const int T = in_sizes[0] / INP;
    lstm_r10_kernel<<<1, NTHREADS>>>(
        (const float*)d_in[0],
        (const float*)d_in[1], (const float*)d_in[2],
        (const float*)d_in[3], (const float*)d_in[4],
        (const float*)d_in[5], (const float*)d_in[6],
        (const float*)d_in[7], (const float*)d_in[8],
        (const float*)d_in[9], (const float*)d_in[10],
        (float*)d_out, T);
}

// round 11
// speedup vs baseline: 1.4903x; 1.4903x over previous
#include <cuda_runtime.h>

// 2-layer LSTM (H=50), T=65536 serial steps, one persistent CTA, 224 threads.
// R8 shuffle-quad skeleton, with the redundant per-thread y-dot eliminated:
// in Phase B every lane holds h2v of its unit, so a 1-FMA + 3-butterfly-shfl
// per-warp reduction produces ypart[w]; Phase A reconstructs
// y = bo + sum(ypart[0..7]) in ~10 instrs instead of a 50-dim dot.
//   Phase A: y from ypart; err; g1K = a1p + w7K*err; act/shfl/cell1 -> sh1
//            q = bb2K + Whh2@h2(s-1) (carried); x(s+1) dot seeded
//   BAR_A
//   Phase B: r = Wih2@h1; g2K = q+r; act/shfl/cell2 -> sh2; a1p(s+1) via
//            Whh1@h1; py reduce -> ypart[w]
//   BAR_B

#define HDIM     50
#define INP      8
#define CHUNK    1024
#define NTHREADS 224

typedef unsigned long long u64;

__device__ __forceinline__ u64 pk2(float lo, float hi) {
    u64 r; asm("mov.b64 %0, {%1,%2};" : "=l"(r) : "f"(lo), "f"(hi)); return r;
}
__device__ __forceinline__ float2 upk2(u64 v) {
    float2 f; asm("mov.b64 {%0,%1}, %2;" : "=f"(f.x), "=f"(f.y) : "l"(v)); return f;
}
__device__ __forceinline__ u64 ffma2(u64 a, u64 b, u64 c) {
    u64 d; asm("fma.rn.f32x2 %0, %1, %2, %3;" : "=l"(d) : "l"(a), "l"(b), "l"(c)); return d;
}
__device__ __forceinline__ u64 add2(u64 a, u64 b) {
    u64 d; asm("add.rn.f32x2 %0, %1, %2;" : "=l"(d) : "l"(a), "l"(b)); return d;
}
__device__ __forceinline__ float tanha(float x) {
    float r; asm("tanh.approx.f32 %0, %1;" : "=f"(r) : "f"(x)); return r;
}

__global__ __launch_bounds__(NTHREADS, 1)
void lstm_r11_kernel(const float* __restrict__ input_seq,
                     const float* __restrict__ W_ih1, const float* __restrict__ W_hh1,
                     const float* __restrict__ b_ih1, const float* __restrict__ b_hh1,
                     const float* __restrict__ W_ih2, const float* __restrict__ W_hh2,
                     const float* __restrict__ b_ih2, const float* __restrict__ b_hh2,
                     const float* __restrict__ W_out, const float* __restrict__ b_out,
                     float* __restrict__ out, int T)
{
    __shared__ __align__(16) float sh1[52];    // h1(s), [50..51]=0
    __shared__ __align__(16) float sh2[52];    // h2(s), [50..51]=0
    __shared__ __align__(16) float ypart[8];   // per-warp wout.h2 partials, [7]=0
    __shared__ __align__(16) float xbuf[(CHUNK + 1) * INP];

    const int t = threadIdx.x;
    const int w = t >> 5;
    const int l = t & 31;
    const int k = l >> 3;                 // gate kind: 0=i 1=f 2=g 3=o
    const int j0 = l & 7;                 // unit-within-warp
    const int uraw = w * 8 + j0;
    const bool uvalid = (uraw < HDIM);
    const int u = uvalid ? uraw : (HDIM - 1);
    const int row = k * HDIM + u;

    // activation: act(x) = fmaf(tanha(K*x), K, A); K folded into the weights
    const float actK = (k == 2) ? 1.0f : 0.5f;
    const float actA = (k == 2) ? 0.0f : 0.5f;

    // ---- per-thread full-row weights, pre-scaled by actK (f32x2; [25]=pad)
    u64 wx[3], wh1[26], wi2[26], wh2[26];
    float w6K, w7K, bb1K, bb2K;
    {
        const float* r1 = W_ih1 + row * INP;
        wx[0] = pk2(actK * r1[0], actK * r1[1]);
        wx[1] = pk2(actK * r1[2], actK * r1[3]);
        wx[2] = pk2(actK * r1[4], actK * r1[5]);
        w6K = actK * r1[6]; w7K = actK * r1[7];
        const float* r2 = W_hh1 + row * HDIM;
        const float* r3 = W_ih2 + row * HDIM;
        const float* r4 = W_hh2 + row * HDIM;
        #pragma unroll
        for (int j = 0; j < 25; ++j) {
            wh1[j] = pk2(actK * r2[2*j], actK * r2[2*j+1]);
            wi2[j] = pk2(actK * r3[2*j], actK * r3[2*j+1]);
            wh2[j] = pk2(actK * r4[2*j], actK * r4[2*j+1]);
        }
        wh1[25] = 0ULL; wi2[25] = 0ULL; wh2[25] = 0ULL;
        bb1K = actK * (b_ih1[row] + b_hh1[row]);
        bb2K = actK * (b_ih2[row] + b_hh2[row]);
    }
    const float bo = b_out[0];
    // wout contribution only from k==0 lanes with valid units
    const float wout_u = ((l >> 3) == 0 && uraw < HDIM) ? W_out[uraw] : 0.0f;
    if (t < 52) { sh1[t] = 0.0f; sh2[t] = 0.0f; }
    if (t < 8)  ypart[t] = 0.0f;

    float c1 = 0.0f, c2 = 0.0f, err = 0.0f, a1p = 0.0f;
    float x7_use = 0.0f, x7_next = 0.0f;
    __syncthreads();

    #pragma unroll 1
    for (int s = 0; s < T; ++s) {
        const int lo = s & (CHUNK - 1);
        if (lo == 0) {
            // old xbuf fully consumed at BAR_B of step s-1
            const float4* src = (const float4*)(input_seq + (size_t)s * INP);
            float4* dst = (float4*)xbuf;
            int n4 = (CHUNK + 1) * 2;
            int rem4 = (T - s) * 2;
            if (rem4 < n4) n4 = rem4;
            for (int i = t; i < n4; i += NTHREADS) dst[i] = src[i];
            __syncthreads();
            if (s == 0) {
                // bootstrap a1p(0) = K*(bb1 + W_ih1 @ x(0)[0..6]); x7_next = x(0)[7]
                float4 xa = *(const float4*)(xbuf);
                float4 xb = *(const float4*)(xbuf + 4);
                u64 a0 = ffma2(wx[0], pk2(xa.x, xa.y), pk2(bb1K, 0.0f));
                u64 a1 = ffma2(wx[1], pk2(xa.z, xa.w), pk2(w6K * xb.z, 0.0f));
                a0 = ffma2(wx[2], pk2(xb.x, xb.y), a0);
                float2 f = upk2(add2(a0, a1));
                a1p = f.x + f.y;
                x7_next = xb.w;
            }
        }

        // ================= Phase A =================
        // x(s+1) early loads + W_ih1@x FMAs (off-path; carried into Phase B)
        const float* xn = &xbuf[(lo + 1) * INP];
        float4 xa = *(const float4*)(xn);
        float4 xb = *(const float4*)(xn + 4);
        u64 a0 = ffma2(wx[0], pk2(xa.x, xa.y), pk2(bb1K, 0.0f));
        u64 a1 = ffma2(wx[1], pk2(xa.z, xa.w), pk2(w6K * xb.z, 0.0f));
        a0 = ffma2(wx[2], pk2(xb.x, xb.y), a0);

        // y(s-1) from per-warp partials (tiny chain instead of 50-dim dot)
        float4 yp0 = *(const float4*)(ypart);
        float4 yp1 = *(const float4*)(ypart + 4);
        float y = bo + (((yp0.x + yp0.y) + (yp0.z + yp0.w)) +
                        ((yp1.x + yp1.y) + (yp1.z + yp1.w)));
        err = (s != 0) ? fmaf(0.1f, x7_use - y, 0.9f * err) : 0.0f;
        if (t == 0 && s != 0) out[s - 1] = y;

        // W_hh2 @ h2(s-1), 4 ILP chains (carried across BAR_A)
        u64 q0 = pk2(bb2K, 0.0f), q1 = pk2(0.0f, 0.0f), q2 = q1, q3 = q1;
        {
            const float4* hv = (const float4*)sh2;
            #pragma unroll
            for (int j = 0; j < 6; ++j) {
                float4 ha = hv[2*j];
                float4 hb = hv[2*j+1];
                q0 = ffma2(wh2[4*j],     pk2(ha.x, ha.y), q0);
                q1 = ffma2(wh2[4*j + 1], pk2(ha.z, ha.w), q1);
                q2 = ffma2(wh2[4*j + 2], pk2(hb.x, hb.y), q2);
                q3 = ffma2(wh2[4*j + 3], pk2(hb.z, hb.w), q3);
            }
            float4 hc = hv[12];
            q0 = ffma2(wh2[24], pk2(hc.x, hc.y), q0);
            q1 = ffma2(wh2[25], pk2(hc.z, hc.w), q1);
        }
        // gates1 finish + activation + quad shuffle + cell1
        {
            float g1K = fmaf(w7K, err, a1p);
            float v0 = fmaf(tanha(g1K), actK, actA);
            float I = __shfl_sync(0xffffffffu, v0, j0);
            float F = __shfl_sync(0xffffffffu, v0, j0 + 8);
            float G = __shfl_sync(0xffffffffu, v0, j0 + 16);
            float O = __shfl_sync(0xffffffffu, v0, j0 + 24);
            c1 = fmaf(F, c1, I * G);
            float h1v = O * tanha(c1);
            if (k == 0 && uvalid) sh1[u] = h1v;
        }
        __syncthreads();   // BAR_A: h1(s) ready

        // ================= Phase B =================
        // one pass over sh1 feeds W_ih2@h1 (4 chains) AND W_hh1@h1 (2 chains)
        u64 r0 = pk2(0.0f, 0.0f), r1 = r0, r2 = r0, r3 = r0;
        {
            const float4* hv = (const float4*)sh1;
            #pragma unroll
            for (int j = 0; j < 6; ++j) {
                float4 ha = hv[2*j];
                float4 hb = hv[2*j+1];
                u64 hal = pk2(ha.x, ha.y), hah = pk2(ha.z, ha.w);
                u64 hbl = pk2(hb.x, hb.y), hbh = pk2(hb.z, hb.w);
                r0 = ffma2(wi2[4*j],     hal, r0);
                r1 = ffma2(wi2[4*j + 1], hah, r1);
                r2 = ffma2(wi2[4*j + 2], hbl, r2);
                r3 = ffma2(wi2[4*j + 3], hbh, r3);
                a0 = ffma2(wh1[4*j],     hal, a0);
                a1 = ffma2(wh1[4*j + 1], hah, a1);
                a0 = ffma2(wh1[4*j + 2], hbl, a0);
                a1 = ffma2(wh1[4*j + 3], hbh, a1);
            }
            float4 hc = hv[12];
            u64 hcl = pk2(hc.x, hc.y), hch = pk2(hc.z, hc.w);
            r0 = ffma2(wi2[24], hcl, r0);
            r1 = ffma2(wi2[25], hch, r1);
            a0 = ffma2(wh1[24], hcl, a0);
            a1 = ffma2(wh1[25], hch, a1);
        }
        {
            u64 m = add2(add2(add2(q0, q1), add2(q2, q3)),
                         add2(add2(r0, r1), add2(r2, r3)));
            float2 mf = upk2(m);
            float g2K = mf.x + mf.y;
            float2 af = upk2(add2(a0, a1));
            a1p = af.x + af.y;                                  // K*gates1-partial(s+1)
            float v0 = fmaf(tanha(g2K), actK, actA);
            float I = __shfl_sync(0xffffffffu, v0, j0);
            float F = __shfl_sync(0xffffffffu, v0, j0 + 8);
            float G = __shfl_sync(0xffffffffu, v0, j0 + 16);
            float O = __shfl_sync(0xffffffffu, v0, j0 + 24);
            c2 = fmaf(F, c2, I * G);
            float h2v = O * tanha(c2);
            if (k == 0 && uvalid) sh2[u] = h2v;
            // per-warp wout.h2 partial: reduce over the 8 k==0 lanes
            float py = wout_u * h2v;            // zero on k!=0 / invalid lanes
            py += __shfl_xor_sync(0xffffffffu, py, 1);
            py += __shfl_xor_sync(0xffffffffu, py, 2);
            py += __shfl_xor_sync(0xffffffffu, py, 4);
            if (l == 0) ypart[w] = py;
        }
        x7_use = x7_next;          // x7(s-1) -> x7(s) for Phase A(s+1)
        x7_next = xb.w;            // x7(s+1)
        __syncthreads();   // BAR_B: h2(s), ypart(s), a1p(s+1) ready
    }

    // epilogue: y(T-1) from final ypart
    if (t == 0) {
        float y = bo;
        #pragma unroll
        for (int j = 0; j < 8; ++j) y += ypart[j];
        out[T - 1] = y;
    }
}

extern "C" void kernel_launch(void* const* d_in, const int* in_sizes, int n_in,
                              void* d_out, int out_size) {
    const int T = in_sizes[0] / INP;
    lstm_r11_kernel<<<1, NTHREADS>>>(
        (const float*)d_in[0],
        (const float*)d_in[1], (const float*)d_in[2],
        (const float*)d_in[3], (const float*)d_in[4],
        (const float*)d_in[5], (const float*)d_in[6],
        (const float*)d_in[7], (const float*)d_in[8],
        (const float*)d_in[9], (const float*)d_in[10],
        (float*)d_out, T);
}

// round 12
// speedup vs baseline: 1.5178x; 1.0184x over previous
#include <cuda_runtime.h>

// 2-layer LSTM (H=50), T=65536 serial steps, one persistent CTA, 256 threads.
// R11 skeleton (shuffle-quad, 2 barriers, ypart y-reduction) rebalanced to 8
// full warps: warp w covers units u = 6w + j0 (j0 in 0..7) -> all 50 units
// covered with 2-unit overlaps; duplicated units compute identical results
// from shared state; a writer mask (j0<6 || w==7) picks the unique storer /
// ypart contributor. Every SMSP now holds exactly 2 warps (was 2/2/2/1) and
// every lane owns a valid gate row.

#define HDIM     50
#define INP      8
#define CHUNK    1024
#define NTHREADS 256

typedef unsigned long long u64;

__device__ __forceinline__ u64 pk2(float lo, float hi) {
    u64 r; asm("mov.b64 %0, {%1,%2};" : "=l"(r) : "f"(lo), "f"(hi)); return r;
}
__device__ __forceinline__ float2 upk2(u64 v) {
    float2 f; asm("mov.b64 {%0,%1}, %2;" : "=f"(f.x), "=f"(f.y) : "l"(v)); return f;
}
__device__ __forceinline__ u64 ffma2(u64 a, u64 b, u64 c) {
    u64 d; asm("fma.rn.f32x2 %0, %1, %2, %3;" : "=l"(d) : "l"(a), "l"(b), "l"(c)); return d;
}
__device__ __forceinline__ u64 add2(u64 a, u64 b) {
    u64 d; asm("add.rn.f32x2 %0, %1, %2;" : "=l"(d) : "l"(a), "l"(b)); return d;
}
__device__ __forceinline__ float tanha(float x) {
    float r; asm("tanh.approx.f32 %0, %1;" : "=f"(r) : "f"(x)); return r;
}

__global__ __launch_bounds__(NTHREADS, 1)
void lstm_r12_kernel(const float* __restrict__ input_seq,
                     const float* __restrict__ W_ih1, const float* __restrict__ W_hh1,
                     const float* __restrict__ b_ih1, const float* __restrict__ b_hh1,
                     const float* __restrict__ W_ih2, const float* __restrict__ W_hh2,
                     const float* __restrict__ b_ih2, const float* __restrict__ b_hh2,
                     const float* __restrict__ W_out, const float* __restrict__ b_out,
                     float* __restrict__ out, int T)
{
    __shared__ __align__(16) float sh1[52];    // h1(s), [50..51]=0
    __shared__ __align__(16) float sh2[52];    // h2(s), [50..51]=0
    __shared__ __align__(16) float ypart[8];   // per-warp wout.h2 partials
    __shared__ __align__(16) float xbuf[(CHUNK + 1) * INP];

    const int t = threadIdx.x;
    const int w = t >> 5;
    const int l = t & 31;
    const int k = l >> 3;                 // gate kind: 0=i 1=f 2=g 3=o
    const int j0 = l & 7;                 // unit-within-warp
    const int u = 6 * w + j0;             // unit 0..49 (overlapping coverage)
    const bool writer = (j0 < 6) || (w == 7);   // unique owner of unit u
    const int row = k * HDIM + u;

    // activation: act(x) = fmaf(tanha(K*x), K, A); K folded into the weights
    const float actK = (k == 2) ? 1.0f : 0.5f;
    const float actA = (k == 2) ? 0.0f : 0.5f;

    // ---- per-thread full-row weights, pre-scaled by actK (f32x2; [25]=pad)
    u64 wx[3], wh1[26], wi2[26], wh2[26];
    float w6K, w7K, bb1K, bb2K;
    {
        const float* r1 = W_ih1 + row * INP;
        wx[0] = pk2(actK * r1[0], actK * r1[1]);
        wx[1] = pk2(actK * r1[2], actK * r1[3]);
        wx[2] = pk2(actK * r1[4], actK * r1[5]);
        w6K = actK * r1[6]; w7K = actK * r1[7];
        const float* r2 = W_hh1 + row * HDIM;
        const float* r3 = W_ih2 + row * HDIM;
        const float* r4 = W_hh2 + row * HDIM;
        #pragma unroll
        for (int j = 0; j < 25; ++j) {
            wh1[j] = pk2(actK * r2[2*j], actK * r2[2*j+1]);
            wi2[j] = pk2(actK * r3[2*j], actK * r3[2*j+1]);
            wh2[j] = pk2(actK * r4[2*j], actK * r4[2*j+1]);
        }
        wh1[25] = 0ULL; wi2[25] = 0ULL; wh2[25] = 0ULL;
        bb1K = actK * (b_ih1[row] + b_hh1[row]);
        bb2K = actK * (b_ih2[row] + b_hh2[row]);
    }
    const float bo = b_out[0];
    // wout contribution only from the k==0 writer lane of each unit
    const float wout_u = (k == 0 && writer) ? W_out[u] : 0.0f;
    if (t < 52) { sh1[t] = 0.0f; sh2[t] = 0.0f; }
    if (t < 8)  ypart[t] = 0.0f;

    float c1 = 0.0f, c2 = 0.0f, err = 0.0f, a1p = 0.0f;
    float x7_use = 0.0f, x7_next = 0.0f;
    __syncthreads();

    #pragma unroll 1
    for (int s = 0; s < T; ++s) {
        const int lo = s & (CHUNK - 1);
        if (lo == 0) {
            // old xbuf fully consumed at BAR_B of step s-1
            const float4* src = (const float4*)(input_seq + (size_t)s * INP);
            float4* dst = (float4*)xbuf;
            int n4 = (CHUNK + 1) * 2;
            int rem4 = (T - s) * 2;
            if (rem4 < n4) n4 = rem4;
            for (int i = t; i < n4; i += NTHREADS) dst[i] = src[i];
            __syncthreads();
            if (s == 0) {
                // bootstrap a1p(0) = K*(bb1 + W_ih1 @ x(0)[0..6]); x7_next = x(0)[7]
                float4 xa = *(const float4*)(xbuf);
                float4 xb = *(const float4*)(xbuf + 4);
                u64 a0 = ffma2(wx[0], pk2(xa.x, xa.y), pk2(bb1K, 0.0f));
                u64 a1 = ffma2(wx[1], pk2(xa.z, xa.w), pk2(w6K * xb.z, 0.0f));
                a0 = ffma2(wx[2], pk2(xb.x, xb.y), a0);
                float2 f = upk2(add2(a0, a1));
                a1p = f.x + f.y;
                x7_next = xb.w;
            }
        }

        // ================= Phase A =================
        // x(s+1) early loads + W_ih1@x FMAs (off-path; carried into Phase B)
        const float* xn = &xbuf[(lo + 1) * INP];
        float4 xa = *(const float4*)(xn);
        float4 xb = *(const float4*)(xn + 4);
        u64 a0 = ffma2(wx[0], pk2(xa.x, xa.y), pk2(bb1K, 0.0f));
        u64 a1 = ffma2(wx[1], pk2(xa.z, xa.w), pk2(w6K * xb.z, 0.0f));
        a0 = ffma2(wx[2], pk2(xb.x, xb.y), a0);

        // y(s-1) from per-warp partials
        float4 yp0 = *(const float4*)(ypart);
        float4 yp1 = *(const float4*)(ypart + 4);
        float y = bo + (((yp0.x + yp0.y) + (yp0.z + yp0.w)) +
                        ((yp1.x + yp1.y) + (yp1.z + yp1.w)));
        err = (s != 0) ? fmaf(0.1f, x7_use - y, 0.9f * err) : 0.0f;
        if (t == 0 && s != 0) out[s - 1] = y;

        // W_hh2 @ h2(s-1), 4 ILP chains (carried across BAR_A)
        u64 q0 = pk2(bb2K, 0.0f), q1 = pk2(0.0f, 0.0f), q2 = q1, q3 = q1;
        {
            const float4* hv = (const float4*)sh2;
            #pragma unroll
            for (int j = 0; j < 6; ++j) {
                float4 ha = hv[2*j];
                float4 hb = hv[2*j+1];
                q0 = ffma2(wh2[4*j],     pk2(ha.x, ha.y), q0);
                q1 = ffma2(wh2[4*j + 1], pk2(ha.z, ha.w), q1);
                q2 = ffma2(wh2[4*j + 2], pk2(hb.x, hb.y), q2);
                q3 = ffma2(wh2[4*j + 3], pk2(hb.z, hb.w), q3);
            }
            float4 hc = hv[12];
            q0 = ffma2(wh2[24], pk2(hc.x, hc.y), q0);
            q1 = ffma2(wh2[25], pk2(hc.z, hc.w), q1);
        }
        // gates1 finish + activation + quad shuffle + cell1
        {
            float g1K = fmaf(w7K, err, a1p);
            float v0 = fmaf(tanha(g1K), actK, actA);
            float I = __shfl_sync(0xffffffffu, v0, j0);
            float F = __shfl_sync(0xffffffffu, v0, j0 + 8);
            float G = __shfl_sync(0xffffffffu, v0, j0 + 16);
            float O = __shfl_sync(0xffffffffu, v0, j0 + 24);
            c1 = fmaf(F, c1, I * G);
            float h1v = O * tanha(c1);
            if (k == 0 && writer) sh1[u] = h1v;
        }
        __syncthreads();   // BAR_A: h1(s) ready

        // ================= Phase B =================
        // one pass over sh1 feeds W_ih2@h1 (4 chains) AND W_hh1@h1 (2 chains)
        u64 r0 = pk2(0.0f, 0.0f), r1 = r0, r2 = r0, r3 = r0;
        {
            const float4* hv = (const float4*)sh1;
            #pragma unroll
            for (int j = 0; j < 6; ++j) {
                float4 ha = hv[2*j];
                float4 hb = hv[2*j+1];
                u64 hal = pk2(ha.x, ha.y), hah = pk2(ha.z, ha.w);
                u64 hbl = pk2(hb.x, hb.y), hbh = pk2(hb.z, hb.w);
                r0 = ffma2(wi2[4*j],     hal, r0);
                r1 = ffma2(wi2[4*j + 1], hah, r1);
                r2 = ffma2(wi2[4*j + 2], hbl, r2);
                r3 = ffma2(wi2[4*j + 3], hbh, r3);
                a0 = ffma2(wh1[4*j],     hal, a0);
                a1 = ffma2(wh1[4*j + 1], hah, a1);
                a0 = ffma2(wh1[4*j + 2], hbl, a0);
                a1 = ffma2(wh1[4*j + 3], hbh, a1);
            }
            float4 hc = hv[12];
            u64 hcl = pk2(hc.x, hc.y), hch = pk2(hc.z, hc.w);
            r0 = ffma2(wi2[24], hcl, r0);
            r1 = ffma2(wi2[25], hch, r1);
            a0 = ffma2(wh1[24], hcl, a0);
            a1 = ffma2(wh1[25], hch, a1);
        }
        {
            u64 m = add2(add2(add2(q0, q1), add2(q2, q3)),
                         add2(add2(r0, r1), add2(r2, r3)));
            float2 mf = upk2(m);
            float g2K = mf.x + mf.y;
            float2 af = upk2(add2(a0, a1));
            a1p = af.x + af.y;                                  // K*gates1-partial(s+1)
            float v0 = fmaf(tanha(g2K), actK, actA);
            float I = __shfl_sync(0xffffffffu, v0, j0);
            float F = __shfl_sync(0xffffffffu, v0, j0 + 8);
            float G = __shfl_sync(0xffffffffu, v0, j0 + 16);
            float O = __shfl_sync(0xffffffffu, v0, j0 + 24);
            c2 = fmaf(F, c2, I * G);
            float h2v = O * tanha(c2);
            if (k == 0 && writer) sh2[u] = h2v;
            // per-warp wout.h2 partial over the 8 k==0 lanes (writer-masked)
            float py = wout_u * h2v;
            py += __shfl_xor_sync(0xffffffffu, py, 1);
            py += __shfl_xor_sync(0xffffffffu, py, 2);
            py += __shfl_xor_sync(0xffffffffu, py, 4);
            if (l == 0) ypart[w] = py;
        }
        x7_use = x7_next;          // x7(s-1) -> x7(s) for Phase A(s+1)
        x7_next = xb.w;            // x7(s+1)
        __syncthreads();   // BAR_B: h2(s), ypart(s), a1p(s+1) ready
    }

    // epilogue: y(T-1) from final ypart
    if (t == 0) {
        float y = bo;
        #pragma unroll
        for (int j = 0; j < 8; ++j) y += ypart[j];
        out[T - 1] = y;
    }
}

extern "C" void kernel_launch(void* const* d_in, const int* in_sizes, int n_in,
                              void* d_out, int out_size) {
    const int T = in_sizes[0] / INP;
    lstm_r12_kernel<<<1, NTHREADS>>>(
        (const float*)d_in[0],
        (const float*)d_in[1], (const float*)d_in[2],
        (const float*)d_in[3], (const float*)d_in[4],
        (const float*)d_in[5], (const float*)d_in[6],
        (const float*)d_in[7], (const float*)d_in[8],
        (const float*)d_in[9], (const float*)d_in[10],
        (float*)d_out, T);
}